// round 17
// baseline (speedup 1.0000x reference)
#include <cuda_runtime.h>
#include <cuda_bf16.h>
#include <cstdint>

#define Dm 1024
#define NELEM (Dm * Dm)

// fp32 scratch
__device__ float g_Cq[NELEM];
__device__ float g_Ck[NELEM];
__device__ float g_Cv[NELEM];
__device__ float g_GhatT[16 * Dm];      // [hs][k]
__device__ float g_dpart[4][Dm * 16];   // k-chunk partials of d[rr][hs]
// bf16 hi/lo split scratch (AO + Wo only)
__device__ __nv_bfloat16 g_Wh[NELEM], g_Wl[NELEM];          // Wo
__device__ __nv_bfloat16 g_AOh[NELEM], g_AOl[NELEM];        // attention out
// int8 two-limb scratch (query + Wq/Wk/Wv), per-row scales
__device__ char g_Qi1[NELEM], g_Qi0[NELEM];
__device__ char g_W3i1[3 * NELEM], g_W3i0[3 * NELEM];
__device__ float g_sQ[1024];
__device__ float g_sW3[3 * 1024];

__device__ __forceinline__ void cp_async16(uint32_t s, const void* g) {
    asm volatile("cp.async.cg.shared.global [%0], [%1], 16;" :: "r"(s), "l"(g));
}
__device__ __forceinline__ uint32_t smem_u32(const void* p) {
    uint32_t a;
    asm("{ .reg .u64 t; cvta.to.shared.u64 t, %1; cvt.u32.u64 %0, t; }" : "=r"(a) : "l"(p));
    return a;
}
__device__ __forceinline__ void mma_bf16(float* c, uint32_t a0, uint32_t a1,
                                         uint32_t a2, uint32_t a3,
                                         uint32_t b0, uint32_t b1) {
    asm volatile(
        "mma.sync.aligned.m16n8k16.row.col.f32.bf16.bf16.f32 "
        "{%0,%1,%2,%3}, {%4,%5,%6,%7}, {%8,%9}, {%0,%1,%2,%3};"
        : "+f"(c[0]), "+f"(c[1]), "+f"(c[2]), "+f"(c[3])
        : "r"(a0), "r"(a1), "r"(a2), "r"(a3), "r"(b0), "r"(b1));
}
__device__ __forceinline__ void mma_s8(int* c, uint32_t a0, uint32_t a1,
                                       uint32_t a2, uint32_t a3,
                                       uint32_t b0, uint32_t b1) {
    asm volatile(
        "mma.sync.aligned.m16n8k32.row.col.s32.s8.s8.s32 "
        "{%0,%1,%2,%3}, {%4,%5,%6,%7}, {%8,%9}, {%0,%1,%2,%3};"
        : "+r"(c[0]), "+r"(c[1]), "+r"(c[2]), "+r"(c[3])
        : "r"(a0), "r"(a1), "r"(a2), "r"(a3), "r"(b0), "r"(b1));
}
__device__ __forceinline__ void ldsm_x4(uint32_t* r, uint32_t addr) {
    asm volatile("ldmatrix.sync.aligned.m8n8.x4.shared.b16 {%0,%1,%2,%3}, [%4];"
                 : "=r"(r[0]), "=r"(r[1]), "=r"(r[2]), "=r"(r[3]) : "r"(addr));
}

// ---------------------------------------------------------------------------
// split + ghat fused. grid (1024, 6) x 256.
//   arr 0..3: int8 two-limb per-row quantize of query/Wq/Wk/Wv (row=blockIdx.x)
//   arr 4:    Wo bf16 hi/lo split
//   arr 5:    GhatT
// ---------------------------------------------------------------------------
__global__ __launch_bounds__(256) void split_ghat(const float* __restrict__ q,
                                                  const float* __restrict__ wq,
                                                  const float* __restrict__ wk,
                                                  const float* __restrict__ wv,
                                                  const float* __restrict__ wo,
                                                  const float* __restrict__ Wr,
                                                  const float* __restrict__ spk_emb) {
    __shared__ float red[128];
    const int arr = blockIdx.y;
    const int tid = threadIdx.x;
    if (arr == 5) {
        if (blockIdx.x >= 128) return;
        const int kc = blockIdx.x & 7;
        const int hs = blockIdx.x >> 3;
        const int kk = tid & 127;
        const int ch = tid >> 7;
        const float* base = Wr + (size_t)(hs * 64 + ch * 32) * 1024 + kc * 128 + kk;
        float s = 0.f;
#pragma unroll
        for (int c2 = 0; c2 < 32; c2++)
            s = fmaf(base[(size_t)c2 * 1024], spk_emb[hs * 64 + ch * 32 + c2], s);
        if (ch) red[kk] = s;
        __syncthreads();
        if (!ch) g_GhatT[hs * 1024 + kc * 128 + kk] = s + red[kk];
        return;
    }
    if (arr == 4) {
        const int idx = (blockIdx.x * 256 + tid) * 4;
        float4 v = *(const float4*)(wo + idx);
        float f[4] = {v.x, v.y, v.z, v.w};
        unsigned short hb[4], lb[4];
#pragma unroll
        for (int i = 0; i < 4; i++) {
            __nv_bfloat16 hv = __float2bfloat16(f[i]);
            __nv_bfloat16 lv = __float2bfloat16(f[i] - __bfloat162float(hv));
            hb[i] = *(unsigned short*)&hv;
            lb[i] = *(unsigned short*)&lv;
        }
        *(ushort4*)(g_Wh + idx) = make_ushort4(hb[0], hb[1], hb[2], hb[3]);
        *(ushort4*)(g_Wl + idx) = make_ushort4(lb[0], lb[1], lb[2], lb[3]);
        return;
    }
    // int8 quantize: one row per block
    const int row = blockIdx.x;
    const float* src = (arr == 0) ? q : (arr == 1) ? wq : (arr == 2) ? wk : wv;
    char* d1 = (arr == 0) ? g_Qi1 : g_W3i1 + (size_t)(arr - 1) * NELEM;
    char* d0 = (arr == 0) ? g_Qi0 : g_W3i0 + (size_t)(arr - 1) * NELEM;
    float* sc = (arr == 0) ? g_sQ : g_sW3 + (arr - 1) * 1024;
    const size_t base = (size_t)row * 1024 + tid * 4;
    float4 v = *(const float4*)(src + base);
    float f[4] = {v.x, v.y, v.z, v.w};
    float m = fmaxf(fmaxf(fabsf(f[0]), fabsf(f[1])), fmaxf(fabsf(f[2]), fabsf(f[3])));
#pragma unroll
    for (int o = 16; o > 0; o >>= 1)
        m = fmaxf(m, __shfl_xor_sync(0xffffffffu, m, o));
    const int lane = tid & 31, w = tid >> 5;
    if (lane == 0) red[w] = m;
    __syncthreads();
    if (tid < 8) {
        float t = red[tid];
#pragma unroll
        for (int o = 4; o > 0; o >>= 1)
            t = fmaxf(t, __shfl_xor_sync(0xffu, t, o));
        if (tid == 0) red[0] = t;
    }
    __syncthreads();
    const float rowmax = red[0];
    const float inv = (rowmax > 0.f) ? (32639.f / rowmax) : 0.f;
    char c1[4], c0[4];
#pragma unroll
    for (int i = 0; i < 4; i++) {
        int qv = __float2int_rn(f[i] * inv);
        int i1 = (qv + 128) >> 8;
        int i0 = qv - (i1 << 8);
        c1[i] = (char)i1;
        c0[i] = (char)i0;
    }
    *(char4*)(d1 + base) = make_char4(c1[0], c1[1], c1[2], c1[3]);
    *(char4*)(d0 + base) = make_char4(c0[0], c0[1], c0[2], c0[3]);
    if (tid == 0) sc[row] = rowmax / 32639.f;
}

// ---------------------------------------------------------------------------
// bf16x3 GEMM core (round-16 winning config) — used by gemm_out only.
// ---------------------------------------------------------------------------
#define RPAD 40
#define A_T (64 * RPAD)
#define B_T (64 * RPAD)
#define OF_AH0 0
#define OF_AH1 A_T
#define OF_AL0 (2 * A_T)
#define OF_AL1 (3 * A_T)
#define OF_BH0 (4 * A_T)
#define OF_BH1 (4 * A_T + B_T)
#define OF_BL0 (4 * A_T + 2 * B_T)
#define OF_BL1 (4 * A_T + 3 * B_T)
#define GEMM_SMEM_BYTES ((4 * A_T + 4 * B_T) * 2)   // 40960

__device__ __forceinline__ void gemm_core(const __nv_bfloat16* __restrict__ Ah,
                                          const __nv_bfloat16* __restrict__ Al,
                                          const __nv_bfloat16* __restrict__ Bh,
                                          const __nv_bfloat16* __restrict__ Bl,
                                          float* __restrict__ C,
                                          const float* __restrict__ bias,
                                          int m0, int n0) {
    extern __shared__ __nv_bfloat16 smb[];
    const uint32_t sb = smem_u32(smb);
    const int tid = threadIdx.x;
    const int wid = tid >> 5, lane = tid & 31;
    const int g = lane >> 2, tg = lane & 3;
    const int wm = wid >> 1, wn = wid & 1;

    const int lane7 = lane & 7;
    const uint32_t aRow = (uint32_t)(wm * 32 + ((lane >> 3) & 1) * 8 + lane7);
    const uint32_t aK4 = (uint32_t)((lane >> 4) * 4);
    const uint32_t bRow = (uint32_t)(wn * 32 + (lane >> 4) * 8 + lane7);
    const uint32_t bK4 = (uint32_t)(((lane >> 3) & 1) * 4);

    float acc[2][4][4];
#pragma unroll
    for (int mt = 0; mt < 2; mt++)
#pragma unroll
        for (int nt = 0; nt < 4; nt++)
#pragma unroll
            for (int r = 0; r < 4; r++) acc[mt][nt][r] = 0.f;

    auto load_tiles = [&](int buf, int k0) {
        const uint32_t ah = sb + (buf ? OF_AH1 : OF_AH0) * 2;
        const uint32_t al = sb + (buf ? OF_AL1 : OF_AL0) * 2;
        const uint32_t bh = sb + (buf ? OF_BH1 : OF_BH0) * 2;
        const uint32_t bl = sb + (buf ? OF_BL1 : OF_BL0) * 2;
#pragma unroll
        for (int i = 0; i < 2; i++) {
            int qd = tid + i * 128;
            int row = qd >> 2, c16 = qd & 3;
            uint32_t off = (uint32_t)(row * RPAD + c16 * 8) * 2;
            const size_t gsrc = (size_t)row * 1024 + k0 + c16 * 8;
            cp_async16(ah + off, Ah + (size_t)m0 * 1024 + gsrc);
            cp_async16(al + off, Al + (size_t)m0 * 1024 + gsrc);
            cp_async16(bh + off, Bh + (size_t)n0 * 1024 + gsrc);
            cp_async16(bl + off, Bl + (size_t)n0 * 1024 + gsrc);
        }
        asm volatile("cp.async.commit_group;");
    };

    load_tiles(0, 0);

    for (int it = 0; it < 32; ++it) {
        const int cur = it & 1;
        asm volatile("cp.async.wait_group 0;");
        __syncthreads();
        if (it + 1 < 32) load_tiles(cur ^ 1, (it + 1) * 32);

        const uint32_t bAH = sb + (cur ? OF_AH1 : OF_AH0) * 2;
        const uint32_t bAL = sb + (cur ? OF_AL1 : OF_AL0) * 2;
        const uint32_t bBH = sb + (cur ? OF_BH1 : OF_BH0) * 2;
        const uint32_t bBL = sb + (cur ? OF_BL1 : OF_BL0) * 2;
#pragma unroll
        for (int kk = 0; kk < 2; kk++) {
            const uint32_t kw = (uint32_t)(kk * 8);
            uint32_t ah4[2][4], al4[2][4];
            uint32_t bh4[2][4], bl4[2][4];
#pragma unroll
            for (int mt = 0; mt < 2; mt++) {
                const uint32_t aoff = ((aRow + (uint32_t)(mt * 16)) * 20 + kw + aK4) * 4;
                ldsm_x4(ah4[mt], bAH + aoff);
                ldsm_x4(al4[mt], bAL + aoff);
            }
#pragma unroll
            for (int p = 0; p < 2; p++) {
                const uint32_t boff = ((bRow + (uint32_t)(p * 16)) * 20 + kw + bK4) * 4;
                ldsm_x4(bh4[p], bBH + boff);
                ldsm_x4(bl4[p], bBL + boff);
            }
#pragma unroll
            for (int p = 0; p < 2; p++)
#pragma unroll
                for (int mt = 0; mt < 2; mt++) {
                    mma_bf16(acc[mt][2 * p], ah4[mt][0], ah4[mt][1], ah4[mt][2],
                             ah4[mt][3], bh4[p][0], bh4[p][1]);
                    mma_bf16(acc[mt][2 * p + 1], ah4[mt][0], ah4[mt][1], ah4[mt][2],
                             ah4[mt][3], bh4[p][2], bh4[p][3]);
                }
#pragma unroll
            for (int p = 0; p < 2; p++)
#pragma unroll
                for (int mt = 0; mt < 2; mt++) {
                    mma_bf16(acc[mt][2 * p], ah4[mt][0], ah4[mt][1], ah4[mt][2],
                             ah4[mt][3], bl4[p][0], bl4[p][1]);
                    mma_bf16(acc[mt][2 * p + 1], ah4[mt][0], ah4[mt][1], ah4[mt][2],
                             ah4[mt][3], bl4[p][2], bl4[p][3]);
                }
#pragma unroll
            for (int p = 0; p < 2; p++)
#pragma unroll
                for (int mt = 0; mt < 2; mt++) {
                    mma_bf16(acc[mt][2 * p], al4[mt][0], al4[mt][1], al4[mt][2],
                             al4[mt][3], bh4[p][0], bh4[p][1]);
                    mma_bf16(acc[mt][2 * p + 1], al4[mt][0], al4[mt][1], al4[mt][2],
                             al4[mt][3], bh4[p][2], bh4[p][3]);
                }
        }
    }

#pragma unroll
    for (int mt = 0; mt < 2; mt++) {
        const int r0 = m0 + wm * 32 + mt * 16 + g;
#pragma unroll
        for (int nt = 0; nt < 4; nt++) {
            const int col = n0 + wn * 32 + nt * 8 + tg * 2;
            float bx = 0.f, by = 0.f;
            if (bias) {
                bx = bias[col];
                by = bias[col + 1];
            }
            float2 v0 = make_float2(acc[mt][nt][0] + bx, acc[mt][nt][1] + by);
            float2 v1 = make_float2(acc[mt][nt][2] + bx, acc[mt][nt][3] + by);
            *(float2*)(C + (size_t)r0 * 1024 + col) = v0;
            *(float2*)(C + (size_t)(r0 + 8) * 1024 + col) = v1;
        }
    }
}

// ---------------------------------------------------------------------------
// int8 two-limb GEMM core: C = sA.sB.(65536*i1i1 + 256*(i1i0+i0i1)) (+bias).
// BM=64, BN=64, BK=64 s8, 128 threads (4 warps 2x2), 16 chunks, double-buffer.
// Rows 64B data padded to 80B (phase r*5 mod 8 -> conflict-free ldmatrix).
// ---------------------------------------------------------------------------
#define I8PAD 80
#define I8_T (64 * I8PAD)   // 5120 bytes per tile
#define I8_A1_0 0
#define I8_A1_1 I8_T
#define I8_A0_0 (2 * I8_T)
#define I8_A0_1 (3 * I8_T)
#define I8_B1_0 (4 * I8_T)
#define I8_B1_1 (5 * I8_T)
#define I8_B0_0 (6 * I8_T)
#define I8_B0_1 (7 * I8_T)
#define I8_SMEM_BYTES (8 * I8_T)   // 40960

__device__ __forceinline__ void gemm_core_i8(const char* __restrict__ A1,
                                             const char* __restrict__ A0,
                                             const char* __restrict__ B1,
                                             const char* __restrict__ B0,
                                             const float* __restrict__ sA,
                                             const float* __restrict__ sB,
                                             float* __restrict__ C,
                                             const float* __restrict__ bias,
                                             int m0, int n0) {
    extern __shared__ __nv_bfloat16 smb[];
    const uint32_t sb = smem_u32(smb);
    const int tid = threadIdx.x;
    const int wid = tid >> 5, lane = tid & 31;
    const int g = lane >> 2, tg = lane & 3;
    const int wm = wid >> 1, wn = wid & 1;

    const int lane7 = lane & 7;
    const uint32_t aRow = (uint32_t)(wm * 32 + ((lane >> 3) & 1) * 8 + lane7);
    const uint32_t aHi = (uint32_t)((lane >> 4) * 16);         // k 16B half
    const uint32_t bRow = (uint32_t)(wn * 32 + (lane >> 4) * 8 + lane7);
    const uint32_t bHi = (uint32_t)(((lane >> 3) & 1) * 16);

    int hi[2][4][4], mid[2][4][4];
#pragma unroll
    for (int mt = 0; mt < 2; mt++)
#pragma unroll
        for (int nt = 0; nt < 4; nt++)
#pragma unroll
            for (int r = 0; r < 4; r++) {
                hi[mt][nt][r] = 0;
                mid[mt][nt][r] = 0;
            }

    auto load_tiles = [&](int buf, int k0) {
        const uint32_t a1 = sb + (buf ? I8_A1_1 : I8_A1_0);
        const uint32_t a0 = sb + (buf ? I8_A0_1 : I8_A0_0);
        const uint32_t b1 = sb + (buf ? I8_B1_1 : I8_B1_0);
        const uint32_t b0 = sb + (buf ? I8_B0_1 : I8_B0_0);
#pragma unroll
        for (int i = 0; i < 2; i++) {
            int qd = tid + i * 128;
            int row = qd >> 2, c16 = qd & 3;
            uint32_t off = (uint32_t)(row * I8PAD + c16 * 16);
            const size_t gsrc = (size_t)row * 1024 + k0 + c16 * 16;
            cp_async16(a1 + off, A1 + (size_t)m0 * 1024 + gsrc);
            cp_async16(a0 + off, A0 + (size_t)m0 * 1024 + gsrc);
            cp_async16(b1 + off, B1 + (size_t)n0 * 1024 + gsrc);
            cp_async16(b0 + off, B0 + (size_t)n0 * 1024 + gsrc);
        }
        asm volatile("cp.async.commit_group;");
    };

    load_tiles(0, 0);

    for (int it = 0; it < 16; ++it) {
        const int cur = it & 1;
        asm volatile("cp.async.wait_group 0;");
        __syncthreads();
        if (it + 1 < 16) load_tiles(cur ^ 1, (it + 1) * 64);

        const uint32_t bA1 = sb + (cur ? I8_A1_1 : I8_A1_0);
        const uint32_t bA0 = sb + (cur ? I8_A0_1 : I8_A0_0);
        const uint32_t bB1 = sb + (cur ? I8_B1_1 : I8_B1_0);
        const uint32_t bB0 = sb + (cur ? I8_B0_1 : I8_B0_0);
#pragma unroll
        for (int kk = 0; kk < 2; kk++) {
            const uint32_t kb = (uint32_t)(kk * 32);
            uint32_t a1f[2][4], a0f[2][4];
            uint32_t b1f[2][4], b0f[2][4];
#pragma unroll
            for (int mt = 0; mt < 2; mt++) {
                const uint32_t aoff = (aRow + (uint32_t)(mt * 16)) * I8PAD + kb + aHi;
                ldsm_x4(a1f[mt], bA1 + aoff);
                ldsm_x4(a0f[mt], bA0 + aoff);
            }
#pragma unroll
            for (int p = 0; p < 2; p++) {
                const uint32_t boff = (bRow + (uint32_t)(p * 16)) * I8PAD + kb + bHi;
                ldsm_x4(b1f[p], bB1 + boff);
                ldsm_x4(b0f[p], bB0 + boff);
            }
            // pass 1: i1*i1 -> hi
#pragma unroll
            for (int p = 0; p < 2; p++)
#pragma unroll
                for (int mt = 0; mt < 2; mt++) {
                    mma_s8(hi[mt][2 * p], a1f[mt][0], a1f[mt][1], a1f[mt][2],
                           a1f[mt][3], b1f[p][0], b1f[p][1]);
                    mma_s8(hi[mt][2 * p + 1], a1f[mt][0], a1f[mt][1], a1f[mt][2],
                           a1f[mt][3], b1f[p][2], b1f[p][3]);
                }
            // pass 2: i1*i0 -> mid
#pragma unroll
            for (int p = 0; p < 2; p++)
#pragma unroll
                for (int mt = 0; mt < 2; mt++) {
                    mma_s8(mid[mt][2 * p], a1f[mt][0], a1f[mt][1], a1f[mt][2],
                           a1f[mt][3], b0f[p][0], b0f[p][1]);
                    mma_s8(mid[mt][2 * p + 1], a1f[mt][0], a1f[mt][1], a1f[mt][2],
                           a1f[mt][3], b0f[p][2], b0f[p][3]);
                }
            // pass 3: i0*i1 -> mid
#pragma unroll
            for (int p = 0; p < 2; p++)
#pragma unroll
                for (int mt = 0; mt < 2; mt++) {
                    mma_s8(mid[mt][2 * p], a0f[mt][0], a0f[mt][1], a0f[mt][2],
                           a0f[mt][3], b1f[p][0], b1f[p][1]);
                    mma_s8(mid[mt][2 * p + 1], a0f[mt][0], a0f[mt][1], a0f[mt][2],
                           a0f[mt][3], b1f[p][2], b1f[p][3]);
                }
        }
    }

#pragma unroll
    for (int mt = 0; mt < 2; mt++) {
        const int r0 = m0 + wm * 32 + mt * 16 + g;
        const float sa0 = sA[r0], sa1 = sA[r0 + 8];
#pragma unroll
        for (int nt = 0; nt < 4; nt++) {
            const int col = n0 + wn * 32 + nt * 8 + tg * 2;
            const float sb0 = sB[col], sb1 = sB[col + 1];
            float bx = 0.f, by = 0.f;
            if (bias) {
                bx = bias[col];
                by = bias[col + 1];
            }
            const int* h = hi[mt][nt];
            const int* m = mid[mt][nt];
            float2 v0, v1;
            v0.x = ((float)h[0] * 65536.f + (float)m[0] * 256.f) * (sa0 * sb0) + bx;
            v0.y = ((float)h[1] * 65536.f + (float)m[1] * 256.f) * (sa0 * sb1) + by;
            v1.x = ((float)h[2] * 65536.f + (float)m[2] * 256.f) * (sa1 * sb0) + bx;
            v1.y = ((float)h[3] * 65536.f + (float)m[3] * 256.f) * (sa1 * sb1) + by;
            *(float2*)(C + (size_t)r0 * 1024 + col) = v0;
            *(float2*)(C + (size_t)(r0 + 8) * 1024 + col) = v1;
        }
    }
}

// ---------------------------------------------------------------------------
// Fused mid kernel, grid (16, 16, 4) x 128: z<3 int8 QKV GEMMs, z==3 dmat.
// ---------------------------------------------------------------------------
__global__ __launch_bounds__(128) void gemm_mid(const float* __restrict__ spk_emb,
                                                const float* __restrict__ relpe) {
    const int z = blockIdx.z;
    if (z < 3) {
        float* C = (z == 0) ? g_Cq : (z == 1) ? g_Ck : g_Cv;
        const float* bias = (z == 0) ? spk_emb : nullptr;
        gemm_core_i8(g_Qi1, g_Qi0,
                     g_W3i1 + (size_t)z * NELEM, g_W3i0 + (size_t)z * NELEM,
                     g_sQ, g_sW3 + z * 1024,
                     C, bias, blockIdx.y * 64, blockIdx.x * 64);
        return;
    }
    const int f = blockIdx.y * 16 + blockIdx.x;
    const int chunk = f & 3;
    const int rrbase = (f >> 2) * 16;
    const int hs = threadIdx.x & 15;
    const int rr0 = rrbase + (threadIdx.x >> 4);
    const int k0 = chunk * 256;
    const float4* arow0 = (const float4*)(relpe + (size_t)rr0 * 1024 + k0);
    const float4* arow1 = (const float4*)(relpe + (size_t)(rr0 + 8) * 1024 + k0);
    const float4* grow = (const float4*)(g_GhatT + (size_t)hs * 1024 + k0);
    float a0 = 0.f, a1 = 0.f, b0 = 0.f, b1 = 0.f;
#pragma unroll 8
    for (int k4 = 0; k4 < 64; k4++) {
        float4 gv = grow[k4];
        float4 x = arow0[k4];
        float4 y = arow1[k4];
        a0 = fmaf(x.x, gv.x, a0);
        a1 = fmaf(x.y, gv.y, a1);
        a0 = fmaf(x.z, gv.z, a0);
        a1 = fmaf(x.w, gv.w, a1);
        b0 = fmaf(y.x, gv.x, b0);
        b1 = fmaf(y.y, gv.y, b1);
        b0 = fmaf(y.z, gv.z, b0);
        b1 = fmaf(y.w, gv.w, b1);
    }
    g_dpart[chunk][rr0 * 16 + hs] = a0 + a1;
    g_dpart[chunk][(rr0 + 8) * 16 + hs] = b0 + b1;
}

__global__ __launch_bounds__(128) void gemm_out(float* __restrict__ out) {
    gemm_core(g_AOh, g_AOl, g_Wh, g_Wl, out, nullptr,
              blockIdx.y * 64, blockIdx.x * 64);
}

// ---------------------------------------------------------------------------
// Fused attention per (b, h) — proven FFMA + warp softmax version.
// ---------------------------------------------------------------------------
#define QS_OFF 0
#define KS_OFF 8320
#define VS_OFF 16640
#define S_OFF 24960
#define E0_OFF 41472
#define E1_OFF 41536
#define CV_OFF 41600
#define SD0_OFF 41728
#define SD1_OFF 41856
#define ATTN_SMEM_FLOATS 41984
#define ATTN_SMEM_BYTES (ATTN_SMEM_FLOATS * 4)

__global__ __launch_bounds__(256) void attn_kernel(const int* __restrict__ spk_mask,
                                                   const float* __restrict__ spk_emb) {
    extern __shared__ float sm[];
    float* Qs = sm + QS_OFF;
    float* Ks = sm + KS_OFF;
    float* Vs = sm + VS_OFF;
    float* S = sm + S_OFF;
    float* e0h = sm + E0_OFF;
    float* e1h = sm + E1_OFF;
    float* cvec = sm + CV_OFF;
    float* sd0 = sm + SD0_OFF;
    float* sd1 = sm + SD1_OFF;

    const int b = blockIdx.x, h = blockIdx.y;
    const int tid = threadIdx.x;

    for (int idx = tid; idx < 128 * 64; idx += 256) {
        int i = idx >> 6, hd = idx & 63;
        size_t g = (size_t)(i * 8 + b) * 1024 + h * 64 + hd;
        Qs[i * 65 + hd] = g_Cq[g];
        Ks[i * 65 + hd] = g_Ck[g];
        Vs[i * 65 + hd] = g_Cv[g];
    }
    if (tid < 64) {
        e0h[tid] = spk_emb[h * 64 + tid];
        e1h[tid] = spk_emb[1024 + h * 64 + tid];
    } else if (tid < 192) {
        int j = tid - 64;
        int off = (j * 8 + b) * 16 + h;
        cvec[j] = (g_dpart[0][off] + g_dpart[1][off]) +
                  (g_dpart[2][off] + g_dpart[3][off]);
    }
    __syncthreads();

    if (tid < 128) {
        float s0 = 0.f, s1 = 0.f;
        const float* qrow = Qs + tid * 65;
#pragma unroll
        for (int k = 0; k < 64; k++) {
            float q = qrow[k];
            s0 = fmaf(q, e0h[k], s0);
            s1 = fmaf(q, e1h[k], s1);
        }
        sd0[tid] = s0;
        sd1[tid] = s1;
    }
    __syncthreads();

    const int ti = tid >> 4, tj = tid & 15;
    float acc[8][8];
#pragma unroll
    for (int a = 0; a < 8; a++)
#pragma unroll
        for (int c2 = 0; c2 < 8; c2++) acc[a][c2] = 0.f;
    for (int k = 0; k < 64; k++) {
        float qa[8], kb[8];
#pragma unroll
        for (int ii = 0; ii < 8; ii++) qa[ii] = Qs[(ti + 16 * ii) * 65 + k];
#pragma unroll
        for (int jj = 0; jj < 8; jj++) kb[jj] = Ks[(tj + 16 * jj) * 65 + k];
#pragma unroll
        for (int ii = 0; ii < 8; ii++)
#pragma unroll
            for (int jj = 0; jj < 8; jj++)
                acc[ii][jj] = fmaf(qa[ii], kb[jj], acc[ii][jj]);
    }
    const int* spm = spk_mask + b * 128 * 128;
#pragma unroll
    for (int ii = 0; ii < 8; ii++) {
        int i = ti + 16 * ii;
#pragma unroll
        for (int jj = 0; jj < 8; jj++) {
            int j = tj + 16 * jj;
            float v;
            if (j <= i) {
                float a2 = spm[i * 128 + j] ? sd1[i] : sd0[i];
                float a3 = cvec[127 - i + j];
                v = (acc[ii][jj] + a2 + a3) * 0.125f;
            } else {
                v = 1e-30f;
            }
            S[i * 129 + j] = v;
        }
    }
    __syncthreads();

    {
        const int lane = tid & 31, w = tid >> 5;
#pragma unroll
        for (int rloc = 0; rloc < 16; rloc++) {
            float* row = S + (w * 16 + rloc) * 129;
            float x0 = row[lane], x1 = row[lane + 32];
            float x2 = row[lane + 64], x3 = row[lane + 96];
            float mx = fmaxf(fmaxf(x0, x1), fmaxf(x2, x3));
#pragma unroll
            for (int o = 16; o > 0; o >>= 1)
                mx = fmaxf(mx, __shfl_xor_sync(0xffffffffu, mx, o));
            float e0 = __expf(x0 - mx), e1 = __expf(x1 - mx);
            float e2 = __expf(x2 - mx), e3 = __expf(x3 - mx);
            float sum = (e0 + e1) + (e2 + e3);
#pragma unroll
            for (int o = 16; o > 0; o >>= 1)
                sum += __shfl_xor_sync(0xffffffffu, sum, o);
            float inv = 1.f / sum;
            row[lane] = e0 * inv;
            row[lane + 32] = e1 * inv;
            row[lane + 64] = e2 * inv;
            row[lane + 96] = e3 * inv;
        }
    }
    __syncthreads();

    const int r = tid >> 3, c = tid & 7;
    float oacc[4][8];
#pragma unroll
    for (int a = 0; a < 4; a++)
#pragma unroll
        for (int c2 = 0; c2 < 8; c2++) oacc[a][c2] = 0.f;
    for (int j = 0; j < 128; j++) {
        float wv[4], vv[8];
#pragma unroll
        for (int ii = 0; ii < 4; ii++) wv[ii] = S[(r + 32 * ii) * 129 + j];
#pragma unroll
        for (int jj = 0; jj < 8; jj++) vv[jj] = Vs[j * 65 + c + 8 * jj];
#pragma unroll
        for (int ii = 0; ii < 4; ii++)
#pragma unroll
            for (int jj = 0; jj < 8; jj++)
                oacc[ii][jj] = fmaf(wv[ii], vv[jj], oacc[ii][jj]);
    }
#pragma unroll
    for (int ii = 0; ii < 4; ii++) {
        int i = r + 32 * ii;
#pragma unroll
        for (int jj = 0; jj < 8; jj++) {
            int hd = c + 8 * jj;
            size_t g = (size_t)(i * 8 + b) * 1024 + h * 64 + hd;
            float v = oacc[ii][jj];
            __nv_bfloat16 hb = __float2bfloat16(v);
            float res = v - __bfloat162float(hb);
            g_AOh[g] = hb;
            g_AOl[g] = __float2bfloat16(res);
        }
    }
}

// ---------------------------------------------------------------------------
extern "C" void kernel_launch(void* const* d_in, const int* in_sizes, int n_in,
                              void* d_out, int out_size) {
    const float* query = (const float*)d_in[0];
    const float* rel_pe = (const float*)d_in[1];
    const float* Wq = (const float*)d_in[3];
    const float* Wk = (const float*)d_in[4];
    const float* Wv = (const float*)d_in[5];
    const float* Wr = (const float*)d_in[6];
    const float* Wo = (const float*)d_in[7];
    const float* spk_emb = (const float*)d_in[8];
    const int* spk_mask = (const int*)d_in[10];
    float* out = (float*)d_out;

    cudaFuncSetAttribute(attn_kernel, cudaFuncAttributeMaxDynamicSharedMemorySize,
                         ATTN_SMEM_BYTES);
    cudaFuncSetAttribute(gemm_mid, cudaFuncAttributeMaxDynamicSharedMemorySize,
                         I8_SMEM_BYTES);
    cudaFuncSetAttribute(gemm_out, cudaFuncAttributeMaxDynamicSharedMemorySize,
                         GEMM_SMEM_BYTES);

    split_ghat<<<dim3(1024, 6), 256>>>(query, Wq, Wk, Wv, Wo, Wr, spk_emb);
    gemm_mid<<<dim3(16, 16, 4), 128, I8_SMEM_BYTES>>>(spk_emb, rel_pe);
    attn_kernel<<<dim3(8, 16), 256, ATTN_SMEM_BYTES>>>(spk_mask, spk_emb);
    gemm_out<<<dim3(16, 16), 128, GEMM_SMEM_BYTES>>>(out);
}